// round 7
// baseline (speedup 1.0000x reference)
#include <cuda_runtime.h>
#include <math.h>

#define BB 2
#define SS 2048
#define CQ 256
#define CC 256
#define DD 50
#define KK 101
#define PP 100
#define JPAD 128

// scratch
__device__ float g_U[BB * SS * CQ];
__device__ float g_p[BB * SS];
__device__ float g_Wpt[CC * JPAD];    // W_p transposed: [c][j], j padded w/ zeros

// ---------------------------------------------------------------------------
// Kernel T: transpose W_p[j][c] -> g_Wpt[c][j] (pad j to 128 with zeros)
// ---------------------------------------------------------------------------
__global__ void __launch_bounds__(256) k_T(const float* __restrict__ W_p) {
    int i = blockIdx.x * 256 + threadIdx.x;       // over CC*JPAD = 32768
    int c = i >> 7, j = i & 127;
    g_Wpt[i] = (j < PP) ? W_p[j * CC + c] : 0.0f;
}

// ---------------------------------------------------------------------------
// Kernel P: p[bs] = S * sigmoid( V_p . tanh(W_p @ c_t[bs]) )
// No SMEM. Lane owns j-quad {4*lane..4*lane+3}; warp handles PRW rows.
// Wpt read as coalesced float4; c_t as uniform-broadcast float4.
// ---------------------------------------------------------------------------
#define PRW 2
__global__ void __launch_bounds__(256) k_p2(const float* __restrict__ c_t,
                                            const float* __restrict__ V_p) {
    const int tid = threadIdx.x, lane = tid & 31, warp = tid >> 5;
    const int row0 = (blockIdx.x * 8 + warp) * PRW;

    float vpv[4];
    #pragma unroll
    for (int t = 0; t < 4; t++) {
        int j = 4 * lane + t;
        vpv[t] = (j < PP) ? V_p[j] : 0.0f;
    }

    float4 acc[PRW];
    #pragma unroll
    for (int r = 0; r < PRW; r++) acc[r] = make_float4(0.f, 0.f, 0.f, 0.f);

    const float* ct0 = c_t + (size_t)row0 * CC;

    for (int c0 = 0; c0 < CC; c0 += 4) {
        float4 ct[PRW];
        #pragma unroll
        for (int r = 0; r < PRW; r++)
            ct[r] = *(const float4*)(ct0 + r * CC + c0);          // uniform bcast
        #pragma unroll
        for (int cc = 0; cc < 4; cc++) {
            const float4 w = *(const float4*)&g_Wpt[(c0 + cc) * JPAD + 4 * lane];
            #pragma unroll
            for (int r = 0; r < PRW; r++) {
                const float s = (cc == 0) ? ct[r].x : (cc == 1) ? ct[r].y
                              : (cc == 2) ? ct[r].z : ct[r].w;
                acc[r].x = fmaf(w.x, s, acc[r].x);
                acc[r].y = fmaf(w.y, s, acc[r].y);
                acc[r].z = fmaf(w.z, s, acc[r].z);
                acc[r].w = fmaf(w.w, s, acc[r].w);
            }
        }
    }

    #pragma unroll
    for (int r = 0; r < PRW; r++) {
        float t = tanhf(acc[r].x) * vpv[0] + tanhf(acc[r].y) * vpv[1]
                + tanhf(acc[r].z) * vpv[2] + tanhf(acc[r].w) * vpv[3];
        #pragma unroll
        for (int o = 16; o > 0; o >>= 1)
            t += __shfl_down_sync(0xffffffffu, t, o);
        if (lane == 0)
            g_p[row0 + r] = (float)SS / (1.0f + expf(-t));
    }
}

// ---------------------------------------------------------------------------
// Kernel U: U[bs, j] = sum_c W_a[c, j] * c_t[bs, c]   (thread owns column j)
// ---------------------------------------------------------------------------
#define TS 16
__global__ void __launch_bounds__(256) k_U(const float* __restrict__ c_t,
                                           const float* __restrict__ W_a) {
    __shared__ float sc[TS][CC];
    const int bs0 = blockIdx.x * TS;
    const int tid = threadIdx.x;

    #pragma unroll
    for (int r = 0; r < TS; r++)
        sc[r][tid] = c_t[(size_t)(bs0 + r) * CC + tid];
    __syncthreads();

    float acc[TS];
    #pragma unroll
    for (int r = 0; r < TS; r++) acc[r] = 0.0f;

    float w0 = W_a[0 * CQ + tid];
    float w1 = W_a[1 * CQ + tid];
    float w2 = W_a[2 * CQ + tid];
    float w3 = W_a[3 * CQ + tid];

    for (int c0 = 0; c0 < CC; c0 += 4) {
        float n0 = 0.f, n1 = 0.f, n2 = 0.f, n3 = 0.f;
        if (c0 + 4 < CC) {
            n0 = W_a[(c0 + 4) * CQ + tid];
            n1 = W_a[(c0 + 5) * CQ + tid];
            n2 = W_a[(c0 + 6) * CQ + tid];
            n3 = W_a[(c0 + 7) * CQ + tid];
        }
        #pragma unroll
        for (int r = 0; r < TS; r++) {
            float4 s = *(const float4*)&sc[r][c0];
            acc[r] += w0 * s.x + w1 * s.y + w2 * s.z + w3 * s.w;
        }
        w0 = n0; w1 = n1; w2 = n2; w3 = n3;
    }
    #pragma unroll
    for (int r = 0; r < TS; r++)
        g_U[(size_t)(bs0 + r) * CQ + tid] = acc[r];
}

// ---------------------------------------------------------------------------
// Kernel 2: one CTA per (b,s).
//   pass 1: 8-lane dots, warp computes 4 k at once (3 shfls / 4 scores)
//   softmax over padded 128 slots (no bounds checks)
//   pass 2: 4 k-groups x 64 channel-quads, 2-deep unroll, SMEM reduce
// ---------------------------------------------------------------------------
__global__ void __launch_bounds__(256) k2_attn(const float* __restrict__ q,
                                               float* __restrict__ out) {
    __shared__ float  su[CQ];
    __shared__ int    srow[128];   // q row index, -1 == invalid; padded to 128
    __shared__ float  sa[128];
    __shared__ float  sw[128];
    __shared__ float4 spart[4][64];

    const int bs = blockIdx.x;
    const int b  = bs >> 11;
    const int tid = threadIdx.x;
    const int warp = tid >> 5, lane = tid & 31;

    const float p = g_p[bs];                       // broadcast load

    su[tid] = g_U[(size_t)bs * CQ + tid];
    if (tid < 128) {
        int row = -1;
        if (tid < KK) {
            float raw = p + (float)(tid - DD) + 1.0f;
            int idx = (int)truncf(raw);
            if (idx < 0) idx = 0;
            if (idx > SS + 1) idx = SS + 1;
            idx = idx % (SS + 1);
            row = idx - 1;
        }
        srow[tid] = row;
    }
    __syncthreads();

    const float* qb = q + (size_t)b * SS * CQ;

    // ---- pass 1: scores. Octet per k; 4 k per warp per iteration ----
    {
        const int sl = lane & 7, sub = lane >> 3;
        float4 u[8];
        #pragma unroll
        for (int i = 0; i < 8; i++)
            u[i] = *(const float4*)&su[(sl + 8 * i) * 4];

        #pragma unroll
        for (int it = 0; it < 4; it++) {
            const int k = warp * 4 + it * 32 + sub;       // covers 0..127
            const int row = srow[k];
            const int rowc = row < 0 ? 0 : row;           // branchless safe row
            const float4* qr = (const float4*)(qb + (size_t)rowc * CQ);
            float d = 0.0f;
            #pragma unroll
            for (int i = 0; i < 8; i++) {
                const float4 a = qr[sl + 8 * i];
                d += a.x * u[i].x + a.y * u[i].y + a.z * u[i].z + a.w * u[i].w;
            }
            d += __shfl_xor_sync(0xffffffffu, d, 4);
            d += __shfl_xor_sync(0xffffffffu, d, 2);
            d += __shfl_xor_sync(0xffffffffu, d, 1);
            if (sl == 0) sa[k] = (row >= 0) ? d : -INFINITY;
        }
    }
    __syncthreads();

    // ---- softmax + gaussian decay over exactly 128 slots (warp 0) ----
    if (warp == 0) {
        const float tp = truncf(p);
        float vals[4];
        float m = -INFINITY;
        #pragma unroll
        for (int t = 0; t < 4; t++) {
            vals[t] = sa[lane + 32 * t];
            m = fmaxf(m, vals[t]);
        }
        #pragma unroll
        for (int o = 16; o > 0; o >>= 1)
            m = fmaxf(m, __shfl_xor_sync(0xffffffffu, m, o));
        float e[4];
        float ssum = 0.0f;
        #pragma unroll
        for (int t = 0; t < 4; t++) {
            e[t] = (vals[t] == -INFINITY) ? 0.0f : expf(vals[t] - m);
            ssum += e[t];
        }
        #pragma unroll
        for (int o = 16; o > 0; o >>= 1)
            ssum += __shfl_xor_sync(0xffffffffu, ssum, o);
        const float inv = 1.0f / ssum;
        #pragma unroll
        for (int t = 0; t < 4; t++) {
            const int k = lane + 32 * t;
            const float dd = ((float)(k - DD) + tp - p) * (1.0f / (float)DD);
            sw[k] = e[t] * inv * expf(-2.0f * dd * dd);
        }
    }
    __syncthreads();

    // ---- pass 2: weighted accumulation, 2-deep k unroll ----
    const int c4 = tid & 63;
    const int g  = tid >> 6;
    float4 a0 = make_float4(0.f, 0.f, 0.f, 0.f);
    float4 a1 = make_float4(0.f, 0.f, 0.f, 0.f);
    int k = g;
    for (; k + 4 < KK; k += 8) {
        {
            int row = srow[k];  row = row < 0 ? 0 : row;
            const float w = sw[k];
            const float4 v = *(const float4*)(qb + (size_t)row * CQ + 4 * c4);
            a0.x = fmaf(w, v.x, a0.x); a0.y = fmaf(w, v.y, a0.y);
            a0.z = fmaf(w, v.z, a0.z); a0.w = fmaf(w, v.w, a0.w);
        }
        {
            int row = srow[k + 4]; row = row < 0 ? 0 : row;
            const float w = sw[k + 4];
            const float4 v = *(const float4*)(qb + (size_t)row * CQ + 4 * c4);
            a1.x = fmaf(w, v.x, a1.x); a1.y = fmaf(w, v.y, a1.y);
            a1.z = fmaf(w, v.z, a1.z); a1.w = fmaf(w, v.w, a1.w);
        }
    }
    if (k < KK) {
        int row = srow[k]; row = row < 0 ? 0 : row;
        const float w = sw[k];
        const float4 v = *(const float4*)(qb + (size_t)row * CQ + 4 * c4);
        a0.x = fmaf(w, v.x, a0.x); a0.y = fmaf(w, v.y, a0.y);
        a0.z = fmaf(w, v.z, a0.z); a0.w = fmaf(w, v.w, a0.w);
    }
    a0.x += a1.x; a0.y += a1.y; a0.z += a1.z; a0.w += a1.w;
    spart[g][c4] = a0;
    __syncthreads();

    if (tid < 64) {
        float4 r0 = spart[0][tid], r1 = spart[1][tid];
        float4 r2 = spart[2][tid], r3 = spart[3][tid];
        float4 r;
        r.x = r0.x + r1.x + r2.x + r3.x;
        r.y = r0.y + r1.y + r2.y + r3.y;
        r.z = r0.z + r1.z + r2.z + r3.z;
        r.w = r0.w + r1.w + r2.w + r3.w;
        ((float4*)(out + (size_t)bs * CQ))[tid] = r;
    }
}

extern "C" void kernel_launch(void* const* d_in, const int* in_sizes, int n_in,
                              void* d_out, int out_size) {
    const float* q   = (const float*)d_in[0];
    const float* c_t = (const float*)d_in[1];
    const float* W_a = (const float*)d_in[2];
    const float* W_p = (const float*)d_in[3];
    const float* V_p = (const float*)d_in[4];
    float* out = (float*)d_out;

    k_T  <<<(CC * JPAD) / 256, 256>>>(W_p);
    k_p2 <<<(BB * SS) / (8 * PRW), 256>>>(c_t, V_p);
    k_U  <<<(BB * SS) / TS, 256>>>(c_t, W_a);
    k2_attn<<<BB * SS, 256>>>(q, out);
}

// round 8
// speedup vs baseline: 1.2192x; 1.2192x over previous
#include <cuda_runtime.h>
#include <math.h>

#define BB 2
#define SS 2048
#define CQ 256
#define CC 256
#define DD 50
#define KK 101
#define PP 100
#define JPAD 128
#define TS 16
#define PRW 2

// scratch
__device__ float g_U[BB * SS * CQ];
__device__ float g_p[BB * SS];
__device__ float g_Wpt[CC * JPAD];    // W_p transposed: [c][j], j padded w/ zeros

// ---------------------------------------------------------------------------
// Kernel T: transpose W_p[j][c] -> g_Wpt[c][j] (pad j to 128 with zeros)
// ---------------------------------------------------------------------------
__global__ void __launch_bounds__(256) k_T(const float* __restrict__ W_p) {
    int i = blockIdx.x * 256 + threadIdx.x;       // over CC*JPAD = 32768
    int c = i >> 7, j = i & 127;
    g_Wpt[i] = (j < PP) ? W_p[j * CC + c] : 0.0f;
}

// ---------------------------------------------------------------------------
// Fused pre-pass. CTAs [0,256): U = c_t @ W_a.  CTAs [256,512): centers p.
// ---------------------------------------------------------------------------
__global__ void __launch_bounds__(256) k_pre(const float* __restrict__ c_t,
                                             const float* __restrict__ W_a,
                                             const float* __restrict__ V_p) {
    __shared__ float sc[TS][CC];
    const int tid = threadIdx.x;

    if (blockIdx.x < 256) {
        // ---------------- U: thread owns output column j = tid --------------
        const int bs0 = blockIdx.x * TS;
        #pragma unroll
        for (int r = 0; r < TS; r++)
            sc[r][tid] = c_t[(size_t)(bs0 + r) * CC + tid];
        __syncthreads();

        float acc[TS];
        #pragma unroll
        for (int r = 0; r < TS; r++) acc[r] = 0.0f;

        float w0 = W_a[0 * CQ + tid];
        float w1 = W_a[1 * CQ + tid];
        float w2 = W_a[2 * CQ + tid];
        float w3 = W_a[3 * CQ + tid];

        for (int c0 = 0; c0 < CC; c0 += 4) {
            float n0 = 0.f, n1 = 0.f, n2 = 0.f, n3 = 0.f;
            if (c0 + 4 < CC) {
                n0 = W_a[(c0 + 4) * CQ + tid];
                n1 = W_a[(c0 + 5) * CQ + tid];
                n2 = W_a[(c0 + 6) * CQ + tid];
                n3 = W_a[(c0 + 7) * CQ + tid];
            }
            #pragma unroll
            for (int r = 0; r < TS; r++) {
                float4 s = *(const float4*)&sc[r][c0];       // broadcast LDS.128
                acc[r] += w0 * s.x + w1 * s.y + w2 * s.z + w3 * s.w;
            }
            w0 = n0; w1 = n1; w2 = n2; w3 = n3;
        }
        #pragma unroll
        for (int r = 0; r < TS; r++)
            g_U[(size_t)(bs0 + r) * CQ + tid] = acc[r];
    } else {
        // ---------------- p: lane owns j-quad, warp handles PRW rows --------
        const int lane = tid & 31, warp = tid >> 5;
        const int row0 = ((blockIdx.x - 256) * 8 + warp) * PRW;

        float vpv[4];
        #pragma unroll
        for (int t = 0; t < 4; t++) {
            int j = 4 * lane + t;
            vpv[t] = (j < PP) ? V_p[j] : 0.0f;
        }

        float4 acc[PRW];
        #pragma unroll
        for (int r = 0; r < PRW; r++) acc[r] = make_float4(0.f, 0.f, 0.f, 0.f);

        const float* ct0 = c_t + (size_t)row0 * CC;

        for (int c0 = 0; c0 < CC; c0 += 4) {
            float4 ct[PRW];
            #pragma unroll
            for (int r = 0; r < PRW; r++)
                ct[r] = *(const float4*)(ct0 + r * CC + c0);      // uniform bcast
            #pragma unroll
            for (int cc = 0; cc < 4; cc++) {
                const float4 w = *(const float4*)&g_Wpt[(c0 + cc) * JPAD + 4 * lane];
                #pragma unroll
                for (int r = 0; r < PRW; r++) {
                    const float s = (cc == 0) ? ct[r].x : (cc == 1) ? ct[r].y
                                  : (cc == 2) ? ct[r].z : ct[r].w;
                    acc[r].x = fmaf(w.x, s, acc[r].x);
                    acc[r].y = fmaf(w.y, s, acc[r].y);
                    acc[r].z = fmaf(w.z, s, acc[r].z);
                    acc[r].w = fmaf(w.w, s, acc[r].w);
                }
            }
        }

        #pragma unroll
        for (int r = 0; r < PRW; r++) {
            float t = tanhf(acc[r].x) * vpv[0] + tanhf(acc[r].y) * vpv[1]
                    + tanhf(acc[r].z) * vpv[2] + tanhf(acc[r].w) * vpv[3];
            #pragma unroll
            for (int o = 16; o > 0; o >>= 1)
                t += __shfl_down_sync(0xffffffffu, t, o);
            if (lane == 0)
                g_p[row0 + r] = (float)SS / (1.0f + expf(-t));
        }
    }
}

// ---------------------------------------------------------------------------
// Kernel 2: one CTA per (b,s).
//   pass 1: octet dots (8 lanes/k, 4 k in flight/warp, 3 shfls) — u from SMEM
//   softmax over padded 128 slots
//   pass 2: 4 k-groups x 64 channel-quads, 2-deep unroll, SMEM reduce
// ---------------------------------------------------------------------------
__global__ void __launch_bounds__(256) k2_attn(const float* __restrict__ q,
                                               float* __restrict__ out) {
    __shared__ float  su[CQ];
    __shared__ int    srow[128];   // q row index, -1 == invalid; padded to 128
    __shared__ float  sa[128];
    __shared__ float  sw[128];
    __shared__ float4 spart[4][64];

    const int bs = blockIdx.x;
    const int b  = bs >> 11;
    const int tid = threadIdx.x;
    const int warp = tid >> 5, lane = tid & 31;

    const float p = g_p[bs];

    su[tid] = g_U[(size_t)bs * CQ + tid];
    if (tid < 128) {
        int row = -1;
        if (tid < KK) {
            float raw = p + (float)(tid - DD) + 1.0f;
            int idx = (int)truncf(raw);
            if (idx < 0) idx = 0;
            if (idx > SS + 1) idx = SS + 1;
            idx = idx % (SS + 1);
            row = idx - 1;
        }
        srow[tid] = row;
    }
    __syncthreads();

    const float* qb = q + (size_t)b * SS * CQ;
    const float4* su4 = (const float4*)su;

    // ---- pass 1: scores. Octet per k; 4 k per warp per iteration ----
    {
        const int sl = lane & 7, sub = lane >> 3;
        #pragma unroll 2
        for (int it = 0; it < 4; it++) {
            const int k = warp * 4 + it * 32 + sub;       // covers 0..127
            const int row = srow[k];
            const int rowc = row < 0 ? 0 : row;           // branchless safe row
            const float4* qr = (const float4*)(qb + (size_t)rowc * CQ);
            float d = 0.0f;
            #pragma unroll
            for (int i = 0; i < 8; i++) {
                const float4 a = qr[sl + 8 * i];
                const float4 u = su4[sl + 8 * i];         // broadcast LDS.128
                d += a.x * u.x + a.y * u.y + a.z * u.z + a.w * u.w;
            }
            d += __shfl_xor_sync(0xffffffffu, d, 4);
            d += __shfl_xor_sync(0xffffffffu, d, 2);
            d += __shfl_xor_sync(0xffffffffu, d, 1);
            if (sl == 0) sa[k] = (row >= 0) ? d : -INFINITY;
        }
    }
    __syncthreads();

    // ---- softmax + gaussian decay over exactly 128 slots (warp 0) ----
    if (warp == 0) {
        const float tp = truncf(p);
        float vals[4];
        float m = -INFINITY;
        #pragma unroll
        for (int t = 0; t < 4; t++) {
            vals[t] = sa[lane + 32 * t];
            m = fmaxf(m, vals[t]);
        }
        #pragma unroll
        for (int o = 16; o > 0; o >>= 1)
            m = fmaxf(m, __shfl_xor_sync(0xffffffffu, m, o));
        float e[4];
        float ssum = 0.0f;
        #pragma unroll
        for (int t = 0; t < 4; t++) {
            e[t] = (vals[t] == -INFINITY) ? 0.0f : expf(vals[t] - m);
            ssum += e[t];
        }
        #pragma unroll
        for (int o = 16; o > 0; o >>= 1)
            ssum += __shfl_xor_sync(0xffffffffu, ssum, o);
        const float inv = 1.0f / ssum;
        #pragma unroll
        for (int t = 0; t < 4; t++) {
            const int k = lane + 32 * t;
            const float dd = ((float)(k - DD) + tp - p) * (1.0f / (float)DD);
            sw[k] = e[t] * inv * expf(-2.0f * dd * dd);
        }
    }
    __syncthreads();

    // ---- pass 2: weighted accumulation, 2-deep k unroll ----
    const int c4 = tid & 63;
    const int g  = tid >> 6;
    float4 a0 = make_float4(0.f, 0.f, 0.f, 0.f);
    float4 a1 = make_float4(0.f, 0.f, 0.f, 0.f);
    int k = g;
    for (; k + 4 < KK; k += 8) {
        {
            int row = srow[k];  row = row < 0 ? 0 : row;
            const float w = sw[k];
            const float4 v = *(const float4*)(qb + (size_t)row * CQ + 4 * c4);
            a0.x = fmaf(w, v.x, a0.x); a0.y = fmaf(w, v.y, a0.y);
            a0.z = fmaf(w, v.z, a0.z); a0.w = fmaf(w, v.w, a0.w);
        }
        {
            int row = srow[k + 4]; row = row < 0 ? 0 : row;
            const float w = sw[k + 4];
            const float4 v = *(const float4*)(qb + (size_t)row * CQ + 4 * c4);
            a1.x = fmaf(w, v.x, a1.x); a1.y = fmaf(w, v.y, a1.y);
            a1.z = fmaf(w, v.z, a1.z); a1.w = fmaf(w, v.w, a1.w);
        }
    }
    if (k < KK) {
        int row = srow[k]; row = row < 0 ? 0 : row;
        const float w = sw[k];
        const float4 v = *(const float4*)(qb + (size_t)row * CQ + 4 * c4);
        a0.x = fmaf(w, v.x, a0.x); a0.y = fmaf(w, v.y, a0.y);
        a0.z = fmaf(w, v.z, a0.z); a0.w = fmaf(w, v.w, a0.w);
    }
    a0.x += a1.x; a0.y += a1.y; a0.z += a1.z; a0.w += a1.w;
    spart[g][c4] = a0;
    __syncthreads();

    if (tid < 64) {
        float4 r0 = spart[0][tid], r1 = spart[1][tid];
        float4 r2 = spart[2][tid], r3 = spart[3][tid];
        float4 r;
        r.x = r0.x + r1.x + r2.x + r3.x;
        r.y = r0.y + r1.y + r2.y + r3.y;
        r.z = r0.z + r1.z + r2.z + r3.z;
        r.w = r0.w + r1.w + r2.w + r3.w;
        ((float4*)(out + (size_t)bs * CQ))[tid] = r;
    }
}

extern "C" void kernel_launch(void* const* d_in, const int* in_sizes, int n_in,
                              void* d_out, int out_size) {
    const float* q   = (const float*)d_in[0];
    const float* c_t = (const float*)d_in[1];
    const float* W_a = (const float*)d_in[2];
    const float* W_p = (const float*)d_in[3];
    const float* V_p = (const float*)d_in[4];
    float* out = (float*)d_out;

    k_T   <<<(CC * JPAD) / 256, 256>>>(W_p);
    k_pre <<<512, 256>>>(c_t, W_a, V_p);
    k2_attn<<<BB * SS, 256>>>(q, out);
}

// round 9
// speedup vs baseline: 1.4117x; 1.1580x over previous
#include <cuda_runtime.h>
#include <math.h>

#define BB 2
#define SS 2048
#define CQ 256
#define CC 256
#define DD 50
#define KK 101
#define PP 100
#define JPAD 128
#define TS 16
#define PRW 2

// scratch
__device__ float g_U[BB * SS * CQ];
__device__ float g_p[BB * SS];
__device__ float g_Wpt[CC * JPAD];    // W_p transposed: [c][j], j padded w/ zeros

// ---------------------------------------------------------------------------
// Kernel T: transpose W_p[j][c] -> g_Wpt[c][j].
// Coalesced LOADS (the thing that stalls), scattered stores (fire-and-forget).
// ---------------------------------------------------------------------------
__global__ void __launch_bounds__(256) k_T(const float* __restrict__ W_p) {
    int i = blockIdx.x * 256 + threadIdx.x;       // over JPAD*CC = 32768
    int j = i >> 8, c = i & 255;                  // consecutive tid -> consecutive c
    float v = (j < PP) ? W_p[j * CC + c] : 0.0f;  // coalesced read
    g_Wpt[c * JPAD + j] = v;                      // scattered write
}

// ---------------------------------------------------------------------------
// Fused pre-pass. CTAs [0,256): U = c_t @ W_a.  CTAs [256,512): centers p.
// ---------------------------------------------------------------------------
__global__ void __launch_bounds__(256) k_pre(const float* __restrict__ c_t,
                                             const float* __restrict__ W_a,
                                             const float* __restrict__ V_p) {
    __shared__ float sc[TS][CC];
    const int tid = threadIdx.x;

    if (blockIdx.x < 256) {
        // ---------------- U: thread owns output column j = tid --------------
        const int bs0 = blockIdx.x * TS;
        #pragma unroll
        for (int r = 0; r < TS; r++)
            sc[r][tid] = c_t[(size_t)(bs0 + r) * CC + tid];
        __syncthreads();

        float acc[TS];
        #pragma unroll
        for (int r = 0; r < TS; r++) acc[r] = 0.0f;

        float w0 = W_a[0 * CQ + tid];
        float w1 = W_a[1 * CQ + tid];
        float w2 = W_a[2 * CQ + tid];
        float w3 = W_a[3 * CQ + tid];

        for (int c0 = 0; c0 < CC; c0 += 4) {
            float n0 = 0.f, n1 = 0.f, n2 = 0.f, n3 = 0.f;
            if (c0 + 4 < CC) {
                n0 = W_a[(c0 + 4) * CQ + tid];
                n1 = W_a[(c0 + 5) * CQ + tid];
                n2 = W_a[(c0 + 6) * CQ + tid];
                n3 = W_a[(c0 + 7) * CQ + tid];
            }
            #pragma unroll
            for (int r = 0; r < TS; r++) {
                float4 s = *(const float4*)&sc[r][c0];       // broadcast LDS.128
                acc[r] += w0 * s.x + w1 * s.y + w2 * s.z + w3 * s.w;
            }
            w0 = n0; w1 = n1; w2 = n2; w3 = n3;
        }
        #pragma unroll
        for (int r = 0; r < TS; r++)
            g_U[(size_t)(bs0 + r) * CQ + tid] = acc[r];
    } else {
        // ---------------- p: lane owns j-quad, warp handles PRW rows --------
        const int lane = tid & 31, warp = tid >> 5;
        const int row0 = ((blockIdx.x - 256) * 8 + warp) * PRW;

        float vpv[4];
        #pragma unroll
        for (int t = 0; t < 4; t++) {
            int j = 4 * lane + t;
            vpv[t] = (j < PP) ? V_p[j] : 0.0f;
        }

        float4 acc[PRW];
        #pragma unroll
        for (int r = 0; r < PRW; r++) acc[r] = make_float4(0.f, 0.f, 0.f, 0.f);

        const float* ct0 = c_t + (size_t)row0 * CC;

        for (int c0 = 0; c0 < CC; c0 += 4) {
            float4 ct[PRW];
            #pragma unroll
            for (int r = 0; r < PRW; r++)
                ct[r] = *(const float4*)(ct0 + r * CC + c0);      // uniform bcast
            #pragma unroll
            for (int cc = 0; cc < 4; cc++) {
                const float4 w = *(const float4*)&g_Wpt[(c0 + cc) * JPAD + 4 * lane];
                #pragma unroll
                for (int r = 0; r < PRW; r++) {
                    const float s = (cc == 0) ? ct[r].x : (cc == 1) ? ct[r].y
                                  : (cc == 2) ? ct[r].z : ct[r].w;
                    acc[r].x = fmaf(w.x, s, acc[r].x);
                    acc[r].y = fmaf(w.y, s, acc[r].y);
                    acc[r].z = fmaf(w.z, s, acc[r].z);
                    acc[r].w = fmaf(w.w, s, acc[r].w);
                }
            }
        }

        #pragma unroll
        for (int r = 0; r < PRW; r++) {
            float t = tanhf(acc[r].x) * vpv[0] + tanhf(acc[r].y) * vpv[1]
                    + tanhf(acc[r].z) * vpv[2] + tanhf(acc[r].w) * vpv[3];
            #pragma unroll
            for (int o = 16; o > 0; o >>= 1)
                t += __shfl_down_sync(0xffffffffu, t, o);
            if (lane == 0)
                g_p[row0 + r] = (float)SS / (1.0f + expf(-t));
        }
    }
}

// ---------------------------------------------------------------------------
// Kernel 2: one CTA per (b,s), SINGLE PASS over the window.
// Each warp streams its k-subset (k = warp + 8t) with online softmax:
// running (m, denom, acc[256] spread 8 floats/lane). Gaussian folded into the
// unnormalized weight. Final 8-way merge via SMEM.
// ---------------------------------------------------------------------------
__device__ __forceinline__ void k2_slot(const float* qb, float p, int k,
                                        bool kvalid, int& row, float& a_out,
                                        float4& x0, float4& x1,
                                        const float4 u0, const float4 u1,
                                        int lane) {
    float raw = p + (float)(k - DD) + 1.0f;
    int idx = (int)truncf(raw);
    idx = idx < 0 ? 0 : (idx > SS + 1 ? SS + 1 : idx);
    idx = (idx == SS + 1) ? 0 : idx;
    row = idx - 1;
    const bool valid = kvalid && (row >= 0);
    const int rowc = row < 0 ? 0 : row;
    const float4* qr = (const float4*)(qb + (size_t)rowc * CQ);
    x0 = qr[lane];
    x1 = qr[lane + 32];
    float d = x0.x * u0.x + x0.y * u0.y + x0.z * u0.z + x0.w * u0.w
            + x1.x * u1.x + x1.y * u1.y + x1.z * u1.z + x1.w * u1.w;
    d += __shfl_xor_sync(0xffffffffu, d, 16);
    d += __shfl_xor_sync(0xffffffffu, d, 8);
    d += __shfl_xor_sync(0xffffffffu, d, 4);
    d += __shfl_xor_sync(0xffffffffu, d, 2);
    d += __shfl_xor_sync(0xffffffffu, d, 1);
    a_out = valid ? d : -INFINITY;
}

__global__ void __launch_bounds__(256) k2_attn(const float* __restrict__ q,
                                               float* __restrict__ out) {
    __shared__ float  sm_m[8], sm_d[8], sm_scale[8];
    __shared__ float4 sm_acc[8 * 64];     // [warp][256 floats]

    const int bs = blockIdx.x;
    const int b  = bs >> 11;
    const int tid = threadIdx.x;
    const int warp = tid >> 5, lane = tid & 31;

    const float p  = g_p[bs];
    const float tp = truncf(p);
    const float* qb = q + (size_t)b * SS * CQ;
    const float4* Ug = (const float4*)(g_U + (size_t)bs * CQ);
    const float4 u0 = Ug[lane], u1 = Ug[lane + 32];

    float m = -1e30f, den = 0.0f;
    float4 acc0 = make_float4(0.f, 0.f, 0.f, 0.f);
    float4 acc1 = make_float4(0.f, 0.f, 0.f, 0.f);

    // pairs t = {0,1},{2,3},...,{10,11}; k = warp + 8t  (k <= 95 < KK always)
    #pragma unroll 2
    for (int t = 0; t < 12; t += 2) {
        const int k1 = warp + 8 * t;
        const int k2 = k1 + 8;
        int row1, row2;
        float a1, a2;
        float4 x0, x1, y0, y1;
        k2_slot(qb, p, k1, true, row1, a1, x0, x1, u0, u1, lane);
        k2_slot(qb, p, k2, true, row2, a2, y0, y1, u0, u1, lane);

        const float mn = fmaxf(m, fmaxf(a1, a2));
        const float s  = expf(m - mn);
        const float e1 = expf(a1 - mn);
        const float e2 = expf(a2 - mn);
        den = den * s + e1 + e2;
        const float dd1 = ((float)(k1 - DD) + tp - p) * (1.0f / (float)DD);
        const float dd2 = ((float)(k2 - DD) + tp - p) * (1.0f / (float)DD);
        const float w1 = e1 * expf(-2.0f * dd1 * dd1);
        const float w2 = e2 * expf(-2.0f * dd2 * dd2);
        acc0.x = fmaf(acc0.x, s, fmaf(w1, x0.x, w2 * y0.x));
        acc0.y = fmaf(acc0.y, s, fmaf(w1, x0.y, w2 * y0.y));
        acc0.z = fmaf(acc0.z, s, fmaf(w1, x0.z, w2 * y0.z));
        acc0.w = fmaf(acc0.w, s, fmaf(w1, x0.w, w2 * y0.w));
        acc1.x = fmaf(acc1.x, s, fmaf(w1, x1.x, w2 * y1.x));
        acc1.y = fmaf(acc1.y, s, fmaf(w1, x1.y, w2 * y1.y));
        acc1.z = fmaf(acc1.z, s, fmaf(w1, x1.z, w2 * y1.z));
        acc1.w = fmaf(acc1.w, s, fmaf(w1, x1.w, w2 * y1.w));
        m = mn;
    }
    // tail: t = 12, k = warp + 96 in [96,103] -> needs k < KK check
    {
        const int k1 = warp + 96;
        int row1;
        float a1;
        float4 x0, x1;
        k2_slot(qb, p, k1, k1 < KK, row1, a1, x0, x1, u0, u1, lane);
        const float mn = fmaxf(m, a1);
        const float s  = expf(m - mn);
        const float e1 = expf(a1 - mn);
        den = den * s + e1;
        const float dd1 = ((float)(k1 - DD) + tp - p) * (1.0f / (float)DD);
        const float w1 = e1 * expf(-2.0f * dd1 * dd1);
        acc0.x = fmaf(acc0.x, s, w1 * x0.x);
        acc0.y = fmaf(acc0.y, s, w1 * x0.y);
        acc0.z = fmaf(acc0.z, s, w1 * x0.z);
        acc0.w = fmaf(acc0.w, s, w1 * x0.w);
        acc1.x = fmaf(acc1.x, s, w1 * x1.x);
        acc1.y = fmaf(acc1.y, s, w1 * x1.y);
        acc1.z = fmaf(acc1.z, s, w1 * x1.z);
        acc1.w = fmaf(acc1.w, s, w1 * x1.w);
        m = mn;
    }

    // merge: every lane of a warp holds identical (m, den); stash partials
    if (lane == 0) { sm_m[warp] = m; sm_d[warp] = den; }
    sm_acc[warp * 64 + lane]      = acc0;    // channels 4*lane .. 4*lane+3
    sm_acc[warp * 64 + 32 + lane] = acc1;    // channels 128+4*lane ..
    __syncthreads();

    if (tid < 8) {
        float M = sm_m[0];
        #pragma unroll
        for (int w = 1; w < 8; w++) M = fmaxf(M, sm_m[w]);
        float Dn = 0.0f;
        #pragma unroll
        for (int w = 0; w < 8; w++) Dn += sm_d[w] * expf(sm_m[w] - M);
        sm_scale[tid] = expf(sm_m[tid] - M) / Dn;
    }
    __syncthreads();

    const float* smf = (const float*)sm_acc;
    float r = 0.0f;
    #pragma unroll
    for (int w = 0; w < 8; w++)
        r = fmaf(smf[w * 256 + tid], sm_scale[w], r);
    out[(size_t)bs * CQ + tid] = r;
}

extern "C" void kernel_launch(void* const* d_in, const int* in_sizes, int n_in,
                              void* d_out, int out_size) {
    const float* q   = (const float*)d_in[0];
    const float* c_t = (const float*)d_in[1];
    const float* W_a = (const float*)d_in[2];
    const float* W_p = (const float*)d_in[3];
    const float* V_p = (const float*)d_in[4];
    float* out = (float*)d_out;

    k_T   <<<(JPAD * CC) / 256, 256>>>(W_p);
    k_pre <<<512, 256>>>(c_t, W_a, V_p);
    k2_attn<<<BB * SS, 256>>>(q, out);
}